// round 4
// baseline (speedup 1.0000x reference)
#include <cuda_runtime.h>

#define SEQ    1024
#define BATCH  64
#define UNITS  512
#define ORDER  128
#define INDIM  512

// scratch (device globals: no allocation allowed)
__device__ float g_xe[BATCH * SEQ];
__device__ int   g_ctr[16];

// ---------------------------------------------------------------------------
// Kernel 1: xe[b,t] = x[b,t,:] @ input_encoders ; also zero barrier counters.
// One warp per row. grid = 65536/8 blocks of 256 threads.
// ---------------------------------------------------------------------------
__global__ void __launch_bounds__(256) xe_kernel(const float* __restrict__ x,
                                                 const float* __restrict__ ie) {
    if (blockIdx.x == 0 && threadIdx.x < 16) g_ctr[threadIdx.x] = 0;
    const int warp = threadIdx.x >> 5;
    const int lane = threadIdx.x & 31;
    const int row  = blockIdx.x * 8 + warp;   // [0, 65536)
    const float* xr = x + (size_t)row * INDIM;
    float s = 0.f;
#pragma unroll
    for (int k = lane; k < INDIM; k += 32) s += xr[k] * ie[k];
#pragma unroll
    for (int o = 16; o > 0; o >>= 1) s += __shfl_down_sync(0xffffffffu, s, o);
    if (lane == 0) g_xe[row] = s;
}

// ---------------------------------------------------------------------------
// Kernel 2: prex = X @ input_kernel  (M=65536, N=512, K=512, fp32)
// BM=128, BN=64, BK=16, 256 threads, 8x4 micro-tile. Writes into d_out.
// ---------------------------------------------------------------------------
__global__ void __launch_bounds__(256) gemm_kernel(const float* __restrict__ A,
                                                   const float* __restrict__ B,
                                                   float* __restrict__ C) {
    __shared__ float As[16][129];   // [k][m], padded
    __shared__ float Bs[16][64];    // [k][n]
    const int m0  = blockIdx.x * 128;
    const int n0  = blockIdx.y * 64;
    const int tid = threadIdx.x;
    const int tx  = tid & 15;       // n dir
    const int ty  = tid >> 4;       // m dir

    float acc[8][4];
#pragma unroll
    for (int i = 0; i < 8; i++)
#pragma unroll
        for (int j = 0; j < 4; j++) acc[i][j] = 0.f;

    for (int k0 = 0; k0 < 512; k0 += 16) {
#pragma unroll
        for (int i = 0; i < 2; i++) {
            int idx = tid + i * 256;         // 0..511
            int row = idx >> 2;              // 0..127
            int c4  = (idx & 3) << 2;        // 0,4,8,12
            float4 v = *reinterpret_cast<const float4*>(&A[(m0 + row) * 512 + k0 + c4]);
            As[c4 + 0][row] = v.x; As[c4 + 1][row] = v.y;
            As[c4 + 2][row] = v.z; As[c4 + 3][row] = v.w;
        }
        {
            int row = tid >> 4, c4 = (tid & 15) << 2;
            *reinterpret_cast<float4*>(&Bs[row][c4]) =
                *reinterpret_cast<const float4*>(&B[(k0 + row) * 512 + n0 + c4]);
        }
        __syncthreads();
#pragma unroll
        for (int k = 0; k < 16; k++) {
            float4 rb = *reinterpret_cast<const float4*>(&Bs[k][tx << 2]);
            float ra[8];
#pragma unroll
            for (int i = 0; i < 8; i++) ra[i] = As[k][(ty << 3) + i];
#pragma unroll
            for (int i = 0; i < 8; i++) {
                acc[i][0] += ra[i] * rb.x;
                acc[i][1] += ra[i] * rb.y;
                acc[i][2] += ra[i] * rb.z;
                acc[i][3] += ra[i] * rb.w;
            }
        }
        __syncthreads();
    }
#pragma unroll
    for (int i = 0; i < 8; i++) {
        float4 o = make_float4(acc[i][0], acc[i][1], acc[i][2], acc[i][3]);
        *reinterpret_cast<float4*>(&C[(m0 + (ty << 3) + i) * 512 + n0 + (tx << 2)]) = o;
    }
}

// ---------------------------------------------------------------------------
// Kernel 3: persistent weight-stationary recurrence.
// grid = (8 unit-slices, 16 batch-groups) = 128 CTAs, 512 threads each.
// CTA (s,g): batches 4g..4g+3, units 64s..64s+63.
// h state flows through d_out itself; per-group barrier via atomic counter.
// m replicated per CTA (bitwise-identical across a group's 8 CTAs).
// ---------------------------------------------------------------------------
struct SmemP2 {
    float  HKs[512 * 64];   // 131072 B  hidden_kernel slice  [k*64+u]
    float  MKs[128 * 64];   //  32768 B  memory_kernel slice  [k*64+u]
    float  h[4 * 512];      //   8192 B  h_{t-1} for 4 batches
    float  m[2 * 4 * 128];  //   4096 B  ping-pong m state
    float4 red[512];        //   8192 B  shared reduction buffer (m + h phases)
    float  he[512];
    float  me[128];
    float  bt[128];
    float  wred[16];
    float  uu[4];
};

__global__ void __launch_bounds__(512) recur_kernel(
    const float* __restrict__ he, const float* __restrict__ me,
    const float* __restrict__ HK, const float* __restrict__ MK,
    const float* __restrict__ AT, const float* __restrict__ BT,
    float* __restrict__ out) {
    extern __shared__ unsigned char smem_raw[];
    SmemP2* s = reinterpret_cast<SmemP2*>(smem_raw);

    const int tid = threadIdx.x;
    const int sl  = blockIdx.x;      // unit slice 0..7
    const int g   = blockIdx.y;      // batch group 0..15
    const int us  = sl * 64;

    // ---- load stationary weights ----
    for (int i = tid; i < 512 * 64; i += 512) {
        int k = i >> 6, u = i & 63;
        s->HKs[i] = HK[k * 512 + us + u];
    }
    for (int i = tid; i < 128 * 64; i += 512) {
        int k = i >> 6, u = i & 63;
        s->MKs[i] = MK[k * 512 + us + u];
    }
    s->he[tid & 511] = he[tid & 511];   // tid covers 0..511
    if (tid < 128) { s->me[tid] = me[tid]; s->bt[tid] = BT[tid]; }
    for (int i = tid; i < 2 * 4 * 128; i += 512) s->m[i] = 0.f;

    // (I + AT) distributed into registers: thread (o = tid>>2, ks = tid&3)
    // holds Am2[ks*32+i][o], i = 0..31
    float am[32];
    {
        const int o = tid >> 2, ks = tid & 3;
#pragma unroll
        for (int i = 0; i < 32; i++) {
            int k = ks * 32 + i;
            am[i] = AT[k * 128 + o] + (k == o ? 1.f : 0.f);
        }
    }
    __syncthreads();

    const int b_u  = tid >> 7, j_u  = tid & 127;   // u-dot layout
    const int o_m  = tid >> 2, ks_m = tid & 3;     // m-partial layout
    const int u_h  = tid & 63, ks_h = tid >> 6;    // h-main layout

    for (int t = 0; t < SEQ; ++t) {
        float* m_old = &s->m[(t & 1) * 512];
        float* m_new = &s->m[((t + 1) & 1) * 512];

        // 1. load h_{t-1} (from d_out, L2-coherent reads)
#pragma unroll
        for (int b = 0; b < 4; b++) {
            float v = 0.f;
            if (t > 0)
                v = __ldcg(&out[((4 * g + b) * SEQ + (t - 1)) * UNITS + tid]);
            s->h[b * 512 + tid] = v;
        }
        __syncthreads();

        // 2. u[b] = xe[b,t] + h_{t-1}[b]·he + m_{t-1}[b]·me
        {
            float p = m_old[b_u * 128 + j_u] * s->me[j_u];
#pragma unroll
            for (int r = 0; r < 4; r++)
                p += s->h[b_u * 512 + j_u + 128 * r] * s->he[j_u + 128 * r];
#pragma unroll
            for (int o = 16; o > 0; o >>= 1) p += __shfl_down_sync(0xffffffffu, p, o);
            if ((tid & 31) == 0) s->wred[tid >> 5] = p;
        }
        __syncthreads();
        if (tid < 4) {
            float v = g_xe[(4 * g + tid) * SEQ + t];
#pragma unroll
            for (int w = 0; w < 4; w++) v += s->wred[tid * 4 + w];
            s->uu[tid] = v;
        }
        __syncthreads();

        // 3. m_t = m_{t-1} @ (I+AT) + u * BT   (Am2 in registers)
        {
            float4 a = make_float4(0.f, 0.f, 0.f, 0.f);
            const int kb = ks_m * 32;
#pragma unroll
            for (int i = 0; i < 32; i++) {
                float w = am[i];
                a.x += m_old[0 * 128 + kb + i] * w;
                a.y += m_old[1 * 128 + kb + i] * w;
                a.z += m_old[2 * 128 + kb + i] * w;
                a.w += m_old[3 * 128 + kb + i] * w;
            }
            s->red[o_m * 4 + ks_m] = a;
        }
        __syncthreads();
        {
            const int b = tid >> 7, o = tid & 127;
            float v = s->uu[b] * s->bt[o];
#pragma unroll
            for (int ks = 0; ks < 4; ks++)
                v += reinterpret_cast<float*>(&s->red[o * 4 + ks])[b];
            m_new[b * 128 + o] = v;
        }
        __syncthreads();

        // 4. h_t = tanh(prex + h_{t-1}@HK + m_t@MK)  — K split 8 ways
        {
            float a0 = 0.f, a1 = 0.f, a2 = 0.f, a3 = 0.f;
            const int k0 = ks_h * 64;
#pragma unroll
            for (int kk = 0; kk < 64; kk += 4) {
                const int k = k0 + kk;
                float4 h0 = *reinterpret_cast<const float4*>(&s->h[0 * 512 + k]);
                float4 h1 = *reinterpret_cast<const float4*>(&s->h[1 * 512 + k]);
                float4 h2 = *reinterpret_cast<const float4*>(&s->h[2 * 512 + k]);
                float4 h3 = *reinterpret_cast<const float4*>(&s->h[3 * 512 + k]);
                float w0 = s->HKs[(k + 0) * 64 + u_h];
                float w1 = s->HKs[(k + 1) * 64 + u_h];
                float w2 = s->HKs[(k + 2) * 64 + u_h];
                float w3 = s->HKs[(k + 3) * 64 + u_h];
                a0 += h0.x * w0 + h0.y * w1 + h0.z * w2 + h0.w * w3;
                a1 += h1.x * w0 + h1.y * w1 + h1.z * w2 + h1.w * w3;
                a2 += h2.x * w0 + h2.y * w1 + h2.z * w2 + h2.w * w3;
                a3 += h3.x * w0 + h3.y * w1 + h3.z * w2 + h3.w * w3;
            }
            const int km = ks_h * 16;
#pragma unroll
            for (int kk = 0; kk < 16; kk += 4) {
                const int k = km + kk;
                float4 m0 = *reinterpret_cast<const float4*>(&m_new[0 * 128 + k]);
                float4 m1 = *reinterpret_cast<const float4*>(&m_new[1 * 128 + k]);
                float4 m2 = *reinterpret_cast<const float4*>(&m_new[2 * 128 + k]);
                float4 m3 = *reinterpret_cast<const float4*>(&m_new[3 * 128 + k]);
                float w0 = s->MKs[(k + 0) * 64 + u_h];
                float w1 = s->MKs[(k + 1) * 64 + u_h];
                float w2 = s->MKs[(k + 2) * 64 + u_h];
                float w3 = s->MKs[(k + 3) * 64 + u_h];
                a0 += m0.x * w0 + m0.y * w1 + m0.z * w2 + m0.w * w3;
                a1 += m1.x * w0 + m1.y * w1 + m1.z * w2 + m1.w * w3;
                a2 += m2.x * w0 + m2.y * w1 + m2.z * w2 + m2.w * w3;
                a3 += m3.x * w0 + m3.y * w1 + m3.z * w2 + m3.w * w3;
            }
            s->red[ks_h * 64 + u_h] = make_float4(a0, a1, a2, a3);
        }
        __syncthreads();
        if (tid < 256) {
            const int b = tid >> 6, u = tid & 63;
            float p = 0.f;
#pragma unroll
            for (int ks = 0; ks < 8; ks++)
                p += reinterpret_cast<float*>(&s->red[ks * 64 + u])[b];
            const int idx = ((4 * g + b) * SEQ + t) * UNITS + us + u;
            float pre = p + out[idx];          // prex written by gemm_kernel
            out[idx] = tanhf(pre);             // in-place: h_t overwrites prex
        }
        // ---- per-group barrier (8 CTAs) ----
        __threadfence();         // make this thread's out-stores L2-visible
        __syncthreads();         // all stores in block done before arrival
        if (tid == 0) {
            atomicAdd(&g_ctr[g], 1);
            const int target = 8 * (t + 1);
            while (*reinterpret_cast<volatile int*>(&g_ctr[g]) < target) { }
        }
        __syncthreads();
    }
}

// ---------------------------------------------------------------------------
extern "C" void kernel_launch(void* const* d_in, const int* in_sizes, int n_in,
                              void* d_out, int out_size) {
    const float* x  = (const float*)d_in[0];   // [64,1024,512]
    const float* ie = (const float*)d_in[1];   // [512,1]
    const float* he = (const float*)d_in[2];   // [512,1]
    const float* me = (const float*)d_in[3];   // [128,1]
    const float* IK = (const float*)d_in[4];   // [512,512]
    const float* HK = (const float*)d_in[5];   // [512,512]
    const float* MK = (const float*)d_in[6];   // [128,512]
    const float* AT = (const float*)d_in[7];   // [128,128]
    const float* BT = (const float*)d_in[8];   // [1,128]
    float* out = (float*)d_out;                // [64,1024,512]

    cudaFuncSetAttribute(recur_kernel,
                         cudaFuncAttributeMaxDynamicSharedMemorySize,
                         (int)sizeof(SmemP2));

    // 1. xe + barrier-counter reset
    xe_kernel<<<(BATCH * SEQ) / 8, 256>>>(x, ie);
    // 2. prex = X @ input_kernel  (into d_out)
    gemm_kernel<<<dim3((BATCH * SEQ) / 128, UNITS / 64), 256>>>(x, IK, out);
    // 3. sequential recurrence, weight-stationary
    recur_kernel<<<dim3(8, 16), 512, sizeof(SmemP2)>>>(he, me, HK, MK, AT, BT, out);
}